// round 1
// baseline (speedup 1.0000x reference)
#include <cuda_runtime.h>
#include <cuda_bf16.h>
#include <math.h>

// ---------------------------------------------------------------------------
// Problem dims (fixed)
// B=8; input [8,3,256,256]; segmap [8,19,256,256]
// L1: reflect-pad conv 3->32, 256x256, IN, lrelu
// L2: conv s2 p1 32->64, 128x128, IN, lrelu
// L3: conv s2 p1 64->128, 64x64, IN, lrelu
// L4: convT s2 p1 op1 128->256, 128x128, IN, lrelu
// L5: reflect-pad conv 256->512, 128x128, tanh
// pool: nearest-downsampled one-hot segmap -> region means -> out [8,19,512]
// ---------------------------------------------------------------------------

#define NB 8
#define NS 19

// scratch (device globals; no allocation allowed)
__device__ float g_act1[NB * 32 * 256 * 256];
__device__ float g_act2[NB * 64 * 128 * 128];
__device__ float g_act3[NB * 128 * 64 * 64];
__device__ float g_act4[NB * 256 * 128 * 128];
__device__ float g_codes[(size_t)NB * 512 * 128 * 128];
__device__ int   g_label[NB * 128 * 128];
__device__ float g_sums[NB * NS * 512];
__device__ int   g_cnt[NB * NS];

__device__ __forceinline__ int refl(int v, int n) {
    return v < 0 ? -v : (v >= n ? 2 * n - 2 - v : v);
}

// ---------------------------------------------------------------------------
// zero counts
// ---------------------------------------------------------------------------
__global__ void k_zero_cnt() {
    int i = threadIdx.x;
    if (i < NB * NS) g_cnt[i] = 0;
}

// ---------------------------------------------------------------------------
// conv1: reflect pad, 3->32, 256x256
// grid (256, NB*32), 256 threads; thread = one output pixel
// ---------------------------------------------------------------------------
__global__ void k_conv1(const float* __restrict__ in, const float* __restrict__ w,
                        const float* __restrict__ bias) {
    int p = blockIdx.y;            // b*32 + co
    int b = p >> 5, co = p & 31;
    __shared__ float ws[27];
    __shared__ float bs;
    if (threadIdx.x < 27) ws[threadIdx.x] = w[co * 27 + threadIdx.x];
    if (threadIdx.x == 0) bs = bias[co];
    __syncthreads();
    int idx = blockIdx.x * 256 + threadIdx.x;   // 0..65535
    int y = idx >> 8, x = idx & 255;
    int ry[3], rx[3];
#pragma unroll
    for (int k = 0; k < 3; k++) { ry[k] = refl(y - 1 + k, 256); rx[k] = refl(x - 1 + k, 256); }
    float acc = bs;
#pragma unroll
    for (int ci = 0; ci < 3; ci++) {
        const float* ip = in + ((size_t)(b * 3 + ci)) * 65536;
#pragma unroll
        for (int ky = 0; ky < 3; ky++) {
            const float* row = ip + ry[ky] * 256;
#pragma unroll
            for (int kx = 0; kx < 3; kx++)
                acc = fmaf(row[rx[kx]], ws[ci * 9 + ky * 3 + kx], acc);
        }
    }
    g_act1[(size_t)p * 65536 + idx] = acc;
}

// ---------------------------------------------------------------------------
// fused instance-norm + leaky relu (in place), one block per (b,c) plane
// ---------------------------------------------------------------------------
__global__ void k_in_lrelu(float* __restrict__ buf, int HW) {
    float* p = buf + (size_t)blockIdx.x * HW;
    float s = 0.f, s2 = 0.f;
    for (int i = threadIdx.x; i < HW; i += 256) {
        float v = p[i];
        s += v;
        s2 = fmaf(v, v, s2);
    }
#pragma unroll
    for (int o = 16; o; o >>= 1) {
        s  += __shfl_down_sync(0xffffffffu, s, o);
        s2 += __shfl_down_sync(0xffffffffu, s2, o);
    }
    __shared__ float sh[16];
    __shared__ float mr[2];
    int wid = threadIdx.x >> 5, lid = threadIdx.x & 31;
    if (lid == 0) { sh[wid] = s; sh[8 + wid] = s2; }
    __syncthreads();
    if (threadIdx.x == 0) {
        float ts = 0.f, t2 = 0.f;
        for (int j = 0; j < 8; j++) { ts += sh[j]; t2 += sh[8 + j]; }
        float inv = 1.0f / (float)HW;
        float m = ts * inv;
        float var = t2 * inv - m * m;
        mr[0] = m;
        mr[1] = rsqrtf(var + 1e-5f);
    }
    __syncthreads();
    float m = mr[0], r = mr[1];
    for (int i = threadIdx.x; i < HW; i += 256) {
        float v = (p[i] - m) * r;
        p[i] = v > 0.f ? v : 0.2f * v;
    }
}

// ---------------------------------------------------------------------------
// strided conv (k=3, stride=2, pad=1), 8 couts per block
// block (16,16); grid (HOUT/16, HOUT/16, NB*COUT/8)
// ---------------------------------------------------------------------------
template <int CIN, int COUT, int HIN>
__global__ void k_conv_s2(const float* __restrict__ in, const float* __restrict__ w,
                          const float* __restrict__ bias, float* __restrict__ out) {
    constexpr int HOUT = HIN / 2;
    int z = blockIdx.z;
    int b = z / (COUT / 8), cog = z % (COUT / 8);
    int tid = threadIdx.y * 16 + threadIdx.x;
    __shared__ float ws[8][CIN * 9];
    for (int idx = tid; idx < 8 * CIN * 9; idx += 256) {
        int co = idx / (CIN * 9), r = idx % (CIN * 9);
        ws[co][r] = w[(size_t)(cog * 8 + co) * CIN * 9 + r];
    }
    __syncthreads();
    int oy = blockIdx.y * 16 + threadIdx.y;
    int ox = blockIdx.x * 16 + threadIdx.x;
    float acc[8];
#pragma unroll
    for (int co = 0; co < 8; co++) acc[co] = bias[cog * 8 + co];
    int iy[3], ix[3];
    float my[3], mx[3];
#pragma unroll
    for (int k = 0; k < 3; k++) {
        int yv = 2 * oy - 1 + k;
        my[k] = ((unsigned)yv < (unsigned)HIN) ? 1.f : 0.f;
        iy[k] = min(max(yv, 0), HIN - 1);
        int xv = 2 * ox - 1 + k;
        mx[k] = ((unsigned)xv < (unsigned)HIN) ? 1.f : 0.f;
        ix[k] = min(max(xv, 0), HIN - 1);
    }
    const float* ibase = in + (size_t)b * CIN * HIN * HIN;
    for (int ci = 0; ci < CIN; ci++) {
        const float* ip = ibase + (size_t)ci * HIN * HIN;
        float iv[9];
#pragma unroll
        for (int ky = 0; ky < 3; ky++) {
            const float* row = ip + iy[ky] * HIN;
#pragma unroll
            for (int kx = 0; kx < 3; kx++)
                iv[ky * 3 + kx] = row[ix[kx]] * (my[ky] * mx[kx]);
        }
#pragma unroll
        for (int co = 0; co < 8; co++) {
            float a = acc[co];
            const float* wp = &ws[co][ci * 9];
#pragma unroll
            for (int k = 0; k < 9; k++) a = fmaf(iv[k], wp[k], a);
            acc[co] = a;
        }
    }
    size_t ob = (((size_t)(b * COUT + cog * 8)) * HOUT + oy) * HOUT + ox;
#pragma unroll
    for (int co = 0; co < 8; co++) out[ob + (size_t)co * HOUT * HOUT] = acc[co];
}

// ---------------------------------------------------------------------------
// transposed conv k=3 s=2 p=1 op=1: in [B,128,64,64] -> out [B,256,128,128]
// w layout (Cin=128, Cout=256, 3, 3) (torch ConvTranspose2d)
// Decomposed by output parity class (cls = py*2+px) so tap sets are uniform.
// grid (4,4, NB*128): z = b*128 + cog*4 + cls ; 8 couts per block.
// ---------------------------------------------------------------------------
__global__ void k_convT(const float* __restrict__ in, const float* __restrict__ w,
                        const float* __restrict__ bias, float* __restrict__ out) {
    int z = blockIdx.z;
    int b = z >> 7;
    int rem = z & 127;
    int cog = rem >> 2, cls = rem & 3;
    int py = cls >> 1, px = cls & 1;
    int tid = threadIdx.y * 16 + threadIdx.x;
    int i0 = blockIdx.y * 16, j0 = blockIdx.x * 16;
    // tap tables: py==0 -> ky=1, iy=i ; py==1 -> ky=0 iy=i+1, ky=2 iy=i
    int nky = py ? 2 : 1, nkx = px ? 2 : 1;
    int kyA[2] = {1, 0}, dyA[2] = {0, 0};
    if (py) { kyA[0] = 0; dyA[0] = 1; kyA[1] = 2; dyA[1] = 0; }
    int kxA[2] = {1, 0}, dxA[2] = {0, 0};
    if (px) { kxA[0] = 0; dxA[0] = 1; kxA[1] = 2; dxA[1] = 0; }

    __shared__ float s_in[4][17][17];
    __shared__ float s_w[4][8][9];
    float acc[8];
#pragma unroll
    for (int co = 0; co < 8; co++) acc[co] = bias[cog * 8 + co];

    for (int cc = 0; cc < 128; cc += 4) {
        __syncthreads();
        for (int idx = tid; idx < 4 * 289; idx += 256) {
            int q = idx / 289, r = idx - q * 289;
            int rr = r / 17, cx = r - rr * 17;
            int gy = i0 + rr, gx = j0 + cx;
            float v = (gy < 64 && gx < 64)
                          ? in[(((size_t)(b * 128 + cc + q)) * 64 + gy) * 64 + gx]
                          : 0.f;
            s_in[q][rr][cx] = v;
        }
        for (int idx = tid; idx < 4 * 72; idx += 256) {
            int q = idx / 72, r = idx - q * 72;
            int co = r / 9, k = r - co * 9;
            s_w[q][co][k] = w[(((size_t)(cc + q)) * 256 + cog * 8 + co) * 9 + k];
        }
        __syncthreads();
#pragma unroll
        for (int q = 0; q < 4; q++) {
            for (int a = 0; a < nky; a++) {
                for (int e = 0; e < nkx; e++) {
                    float iv = s_in[q][threadIdx.y + dyA[a]][threadIdx.x + dxA[e]];
                    int k = kyA[a] * 3 + kxA[e];
#pragma unroll
                    for (int co = 0; co < 8; co++)
                        acc[co] = fmaf(iv, s_w[q][co][k], acc[co]);
                }
            }
        }
    }
    int y = 2 * (i0 + threadIdx.y) + py;
    int x = 2 * (j0 + threadIdx.x) + px;
    size_t ob = (((size_t)(b * 256 + cog * 8)) * 128 + y) * 128 + x;
#pragma unroll
    for (int co = 0; co < 8; co++) out[ob + (size_t)co * 16384] = acc[co];
}

// ---------------------------------------------------------------------------
// conv5: reflect-pad conv 256->512 @128x128 + tanh. The heavy GEMM (309 GF).
// block = 256 thr (16x16 pixels), 16 couts per block, 16 accs/thread.
// grid (8,8, NB*32)
// ---------------------------------------------------------------------------
__global__ __launch_bounds__(256) void k_conv5(const float* __restrict__ in,
                                               const float* __restrict__ w,
                                               const float* __restrict__ bias,
                                               float* __restrict__ out) {
    int z = blockIdx.z;
    int b = z >> 5, cog = z & 31;
    int tid = threadIdx.x;
    int ty = tid >> 4, tx = tid & 15;
    int y0 = blockIdx.y * 16, x0 = blockIdx.x * 16;

    __shared__ float s_in[4][18][18];
    __shared__ float s_w[4][16][9];

    float acc[16];
#pragma unroll
    for (int c = 0; c < 16; c++) acc[c] = 0.f;

    for (int cc = 0; cc < 256; cc += 4) {
        __syncthreads();
        for (int idx = tid; idx < 4 * 324; idx += 256) {
            int q = idx / 324, r = idx - q * 324;
            int yy = r / 18, xx = r - yy * 18;
            int gy = refl(y0 - 1 + yy, 128);
            int gx = refl(x0 - 1 + xx, 128);
            s_in[q][yy][xx] = in[(((size_t)(b * 256 + cc + q)) * 128 + gy) * 128 + gx];
        }
        for (int idx = tid; idx < 4 * 144; idx += 256) {
            int q = idx / 144, r = idx - q * 144;
            int col = r / 9, k = r - col * 9;
            s_w[q][col][k] = w[(((size_t)(cog * 16 + col)) * 256 + cc + q) * 9 + k];
        }
        __syncthreads();
#pragma unroll
        for (int q = 0; q < 4; q++) {
            float iv[9];
#pragma unroll
            for (int dy = 0; dy < 3; dy++)
#pragma unroll
                for (int dx = 0; dx < 3; dx++)
                    iv[dy * 3 + dx] = s_in[q][ty + dy][tx + dx];
#pragma unroll
            for (int col = 0; col < 16; col++) {
                float a = acc[col];
#pragma unroll
                for (int k = 0; k < 9; k++) a = fmaf(iv[k], s_w[q][col][k], a);
                acc[col] = a;
            }
        }
    }
    int y = y0 + ty, x = x0 + tx;
    size_t ob = (((size_t)((size_t)b * 512 + cog * 16)) * 128 + y) * 128 + x;
#pragma unroll
    for (int col = 0; col < 16; col++)
        out[ob + (size_t)col * 16384] = tanhf(acc[col] + bias[cog * 16 + col]);
}

// ---------------------------------------------------------------------------
// labels + counts from segmap (one-hot over S); nearest resize 256->128 = (2h,2w)
// grid (64, NB), 256 threads
// ---------------------------------------------------------------------------
__global__ void k_label(const float* __restrict__ seg) {
    int b = blockIdx.y;
    int i = blockIdx.x * 256 + threadIdx.x;   // 0..16383
    int h = i >> 7, wv = i & 127;
    const float* sp = seg + (size_t)b * NS * 65536 + (2 * h) * 256 + 2 * wv;
    int lab = 0;
#pragma unroll 1
    for (int s = 0; s < NS; s++) {
        if (sp[(size_t)s * 65536] > 0.f) { lab = s; break; }
    }
    g_label[b * 16384 + i] = lab;
    atomicAdd(&g_cnt[b * NS + lab], 1);
}

// ---------------------------------------------------------------------------
// segment-sum pooling: block per (b,c); smem bins [19][8] sub-binned
// grid (NB*512), 256 threads
// ---------------------------------------------------------------------------
__global__ void k_pool(const float* __restrict__ codes) {
    int c = blockIdx.x & 511;
    int b = blockIdx.x >> 9;
    __shared__ float bins[NS * 8];
    if (threadIdx.x < NS * 8) bins[threadIdx.x] = 0.f;
    __syncthreads();
    const float* cp = codes + ((size_t)(b * 512 + c)) * 16384;
    const int* lp = g_label + b * 16384;
    int sub = threadIdx.x & 7;
    for (int i = threadIdx.x; i < 16384; i += 256)
        atomicAdd(&bins[lp[i] * 8 + sub], cp[i]);
    __syncthreads();
    if (threadIdx.x < NS) {
        float s = 0.f;
#pragma unroll
        for (int j = 0; j < 8; j++) s += bins[threadIdx.x * 8 + j];
        g_sums[((size_t)b * NS + threadIdx.x) * 512 + c] = s;
    }
}

// ---------------------------------------------------------------------------
// finalize: out[b,s,c] = cnt>0 ? sums/cnt : 0
// ---------------------------------------------------------------------------
__global__ void k_final(float* __restrict__ out) {
    int idx = blockIdx.x * 256 + threadIdx.x;
    if (idx >= NB * NS * 512) return;
    int bs = idx >> 9;   // b*NS + s
    int cnt = g_cnt[bs];
    out[idx] = cnt > 0 ? g_sums[idx] / (float)cnt : 0.f;
}

// ---------------------------------------------------------------------------
extern "C" void kernel_launch(void* const* d_in, const int* in_sizes, int n_in,
                              void* d_out, int out_size) {
    const float* input  = (const float*)d_in[0];
    const float* segmap = (const float*)d_in[1];
    const float* w1 = (const float*)d_in[2];
    const float* b1 = (const float*)d_in[3];
    const float* w2 = (const float*)d_in[4];
    const float* b2 = (const float*)d_in[5];
    const float* w3 = (const float*)d_in[6];
    const float* b3 = (const float*)d_in[7];
    const float* w4 = (const float*)d_in[8];
    const float* b4 = (const float*)d_in[9];
    const float* w5 = (const float*)d_in[10];
    const float* b5 = (const float*)d_in[11];
    float* out = (float*)d_out;

    float* act1;  cudaGetSymbolAddress((void**)&act1, g_act1);
    float* act2;  cudaGetSymbolAddress((void**)&act2, g_act2);
    float* act3;  cudaGetSymbolAddress((void**)&act3, g_act3);
    float* act4;  cudaGetSymbolAddress((void**)&act4, g_act4);
    float* codes; cudaGetSymbolAddress((void**)&codes, g_codes);

    k_zero_cnt<<<1, 256>>>();

    // L1
    k_conv1<<<dim3(256, NB * 32), 256>>>(input, w1, b1);
    k_in_lrelu<<<NB * 32, 256>>>(act1, 65536);
    // L2
    k_conv_s2<32, 64, 256><<<dim3(8, 8, NB * 8), dim3(16, 16)>>>(act1, w2, b2, act2);
    k_in_lrelu<<<NB * 64, 256>>>(act2, 16384);
    // L3
    k_conv_s2<64, 128, 128><<<dim3(4, 4, NB * 16), dim3(16, 16)>>>(act2, w3, b3, act3);
    k_in_lrelu<<<NB * 128, 256>>>(act3, 4096);
    // L4 (transposed conv)
    k_convT<<<dim3(4, 4, NB * 128), dim3(16, 16)>>>(act3, w4, b4, act4);
    k_in_lrelu<<<NB * 256, 256>>>(act4, 16384);
    // L5 (+tanh)
    k_conv5<<<dim3(8, 8, NB * 32), 256>>>(act4, w5, b5, codes);
    // pooling
    k_label<<<dim3(64, NB), 256>>>(segmap);
    k_pool<<<NB * 512, 256>>>(codes);
    k_final<<<(NB * NS * 512 + 255) / 256, 256>>>(out);
}

// round 2
// speedup vs baseline: 2.1644x; 2.1644x over previous
#include <cuda_runtime.h>
#include <cuda_bf16.h>
#include <math.h>

// ---------------------------------------------------------------------------
// B=8; input [8,3,256,256]; segmap [8,19,256,256]
// L1: reflect-pad conv 3->32, 256x256, IN, lrelu
// L2: conv s2 p1 32->64, 128x128, IN, lrelu
// L3: conv s2 p1 64->128, 64x64, IN, lrelu
// L4: convT s2 p1 op1 128->256, 128x128, IN, lrelu
// L5: reflect-pad conv 256->512, 128x128, tanh   <-- tf32 mma.sync implicit GEMM
// pool: nearest one-hot segmap -> region means -> out [8,19,512]
// ---------------------------------------------------------------------------

#define NB 8
#define NS 19

__device__ float g_act1[NB * 32 * 256 * 256];
__device__ float g_act2[NB * 64 * 128 * 128];
__device__ float g_act3[NB * 128 * 64 * 64];
__device__ float g_act4[NB * 256 * 128 * 128];
__device__ float g_codes[(size_t)NB * 512 * 128 * 128];
__device__ int   g_label[NB * 128 * 128];
__device__ float g_sums[NB * NS * 512];
__device__ int   g_cnt[NB * NS];

__device__ __forceinline__ int refl(int v, int n) {
    return v < 0 ? -v : (v >= n ? 2 * n - 2 - v : v);
}

__device__ __forceinline__ unsigned f2tf(float f) {
    unsigned u;
    asm("cvt.rna.tf32.f32 %0, %1;" : "=r"(u) : "f"(f));
    return u;
}

__device__ __forceinline__ void mma_tf32(float* c, const unsigned* a, const unsigned* b) {
    asm volatile(
        "mma.sync.aligned.m16n8k8.row.col.f32.tf32.tf32.f32 "
        "{%0,%1,%2,%3}, {%4,%5,%6,%7}, {%8,%9}, {%0,%1,%2,%3};"
        : "+f"(c[0]), "+f"(c[1]), "+f"(c[2]), "+f"(c[3])
        : "r"(a[0]), "r"(a[1]), "r"(a[2]), "r"(a[3]), "r"(b[0]), "r"(b[1]));
}

// ---------------------------------------------------------------------------
__global__ void k_zero_cnt() {
    int i = threadIdx.x;
    if (i < NB * NS) g_cnt[i] = 0;
}

// ---------------------------------------------------------------------------
// conv1: reflect pad, 3->32, 256x256
// ---------------------------------------------------------------------------
__global__ void k_conv1(const float* __restrict__ in, const float* __restrict__ w,
                        const float* __restrict__ bias) {
    int p = blockIdx.y;
    int b = p >> 5, co = p & 31;
    __shared__ float ws[27];
    __shared__ float bs;
    if (threadIdx.x < 27) ws[threadIdx.x] = w[co * 27 + threadIdx.x];
    if (threadIdx.x == 0) bs = bias[co];
    __syncthreads();
    int idx = blockIdx.x * 256 + threadIdx.x;
    int y = idx >> 8, x = idx & 255;
    int ry[3], rx[3];
#pragma unroll
    for (int k = 0; k < 3; k++) { ry[k] = refl(y - 1 + k, 256); rx[k] = refl(x - 1 + k, 256); }
    float acc = bs;
#pragma unroll
    for (int ci = 0; ci < 3; ci++) {
        const float* ip = in + ((size_t)(b * 3 + ci)) * 65536;
#pragma unroll
        for (int ky = 0; ky < 3; ky++) {
            const float* row = ip + ry[ky] * 256;
#pragma unroll
            for (int kx = 0; kx < 3; kx++)
                acc = fmaf(row[rx[kx]], ws[ci * 9 + ky * 3 + kx], acc);
        }
    }
    g_act1[(size_t)p * 65536 + idx] = acc;
}

// ---------------------------------------------------------------------------
// fused instance-norm + leaky relu (in place)
// ---------------------------------------------------------------------------
__global__ void k_in_lrelu(float* __restrict__ buf, int HW) {
    float* p = buf + (size_t)blockIdx.x * HW;
    float s = 0.f, s2 = 0.f;
    for (int i = threadIdx.x; i < HW; i += 256) {
        float v = p[i];
        s += v;
        s2 = fmaf(v, v, s2);
    }
#pragma unroll
    for (int o = 16; o; o >>= 1) {
        s  += __shfl_down_sync(0xffffffffu, s, o);
        s2 += __shfl_down_sync(0xffffffffu, s2, o);
    }
    __shared__ float sh[16];
    __shared__ float mr[2];
    int wid = threadIdx.x >> 5, lid = threadIdx.x & 31;
    if (lid == 0) { sh[wid] = s; sh[8 + wid] = s2; }
    __syncthreads();
    if (threadIdx.x == 0) {
        float ts = 0.f, t2 = 0.f;
        for (int j = 0; j < 8; j++) { ts += sh[j]; t2 += sh[8 + j]; }
        float inv = 1.0f / (float)HW;
        float m = ts * inv;
        float var = t2 * inv - m * m;
        mr[0] = m;
        mr[1] = rsqrtf(var + 1e-5f);
    }
    __syncthreads();
    float m = mr[0], r = mr[1];
    for (int i = threadIdx.x; i < HW; i += 256) {
        float v = (p[i] - m) * r;
        p[i] = v > 0.f ? v : 0.2f * v;
    }
}

// ---------------------------------------------------------------------------
// strided conv (k=3, stride=2, pad=1), 8 couts per block
// ---------------------------------------------------------------------------
template <int CIN, int COUT, int HIN>
__global__ void k_conv_s2(const float* __restrict__ in, const float* __restrict__ w,
                          const float* __restrict__ bias, float* __restrict__ out) {
    constexpr int HOUT = HIN / 2;
    int z = blockIdx.z;
    int b = z / (COUT / 8), cog = z % (COUT / 8);
    int tid = threadIdx.y * 16 + threadIdx.x;
    __shared__ float ws[8][CIN * 9];
    for (int idx = tid; idx < 8 * CIN * 9; idx += 256) {
        int co = idx / (CIN * 9), r = idx % (CIN * 9);
        ws[co][r] = w[(size_t)(cog * 8 + co) * CIN * 9 + r];
    }
    __syncthreads();
    int oy = blockIdx.y * 16 + threadIdx.y;
    int ox = blockIdx.x * 16 + threadIdx.x;
    float acc[8];
#pragma unroll
    for (int co = 0; co < 8; co++) acc[co] = bias[cog * 8 + co];
    int iy[3], ix[3];
    float my[3], mx[3];
#pragma unroll
    for (int k = 0; k < 3; k++) {
        int yv = 2 * oy - 1 + k;
        my[k] = ((unsigned)yv < (unsigned)HIN) ? 1.f : 0.f;
        iy[k] = min(max(yv, 0), HIN - 1);
        int xv = 2 * ox - 1 + k;
        mx[k] = ((unsigned)xv < (unsigned)HIN) ? 1.f : 0.f;
        ix[k] = min(max(xv, 0), HIN - 1);
    }
    const float* ibase = in + (size_t)b * CIN * HIN * HIN;
    for (int ci = 0; ci < CIN; ci++) {
        const float* ip = ibase + (size_t)ci * HIN * HIN;
        float iv[9];
#pragma unroll
        for (int ky = 0; ky < 3; ky++) {
            const float* row = ip + iy[ky] * HIN;
#pragma unroll
            for (int kx = 0; kx < 3; kx++)
                iv[ky * 3 + kx] = row[ix[kx]] * (my[ky] * mx[kx]);
        }
#pragma unroll
        for (int co = 0; co < 8; co++) {
            float a = acc[co];
            const float* wp = &ws[co][ci * 9];
#pragma unroll
            for (int k = 0; k < 9; k++) a = fmaf(iv[k], wp[k], a);
            acc[co] = a;
        }
    }
    size_t ob = (((size_t)(b * COUT + cog * 8)) * HOUT + oy) * HOUT + ox;
#pragma unroll
    for (int co = 0; co < 8; co++) out[ob + (size_t)co * HOUT * HOUT] = acc[co];
}

// ---------------------------------------------------------------------------
// transposed conv k=3 s=2 p=1 op=1: [B,128,64,64] -> [B,256,128,128]
// ---------------------------------------------------------------------------
__global__ void k_convT(const float* __restrict__ in, const float* __restrict__ w,
                        const float* __restrict__ bias, float* __restrict__ out) {
    int z = blockIdx.z;
    int b = z >> 7;
    int rem = z & 127;
    int cog = rem >> 2, cls = rem & 3;
    int py = cls >> 1, px = cls & 1;
    int tid = threadIdx.y * 16 + threadIdx.x;
    int i0 = blockIdx.y * 16, j0 = blockIdx.x * 16;
    int nky = py ? 2 : 1, nkx = px ? 2 : 1;
    int kyA[2] = {1, 0}, dyA[2] = {0, 0};
    if (py) { kyA[0] = 0; dyA[0] = 1; kyA[1] = 2; dyA[1] = 0; }
    int kxA[2] = {1, 0}, dxA[2] = {0, 0};
    if (px) { kxA[0] = 0; dxA[0] = 1; kxA[1] = 2; dxA[1] = 0; }

    __shared__ float s_in[4][17][17];
    __shared__ float s_w[4][8][9];
    float acc[8];
#pragma unroll
    for (int co = 0; co < 8; co++) acc[co] = bias[cog * 8 + co];

    for (int cc = 0; cc < 128; cc += 4) {
        __syncthreads();
        for (int idx = tid; idx < 4 * 289; idx += 256) {
            int q = idx / 289, r = idx - q * 289;
            int rr = r / 17, cx = r - rr * 17;
            int gy = i0 + rr, gx = j0 + cx;
            float v = (gy < 64 && gx < 64)
                          ? in[(((size_t)(b * 128 + cc + q)) * 64 + gy) * 64 + gx]
                          : 0.f;
            s_in[q][rr][cx] = v;
        }
        for (int idx = tid; idx < 4 * 72; idx += 256) {
            int q = idx / 72, r = idx - q * 72;
            int co = r / 9, k = r - co * 9;
            s_w[q][co][k] = w[(((size_t)(cc + q)) * 256 + cog * 8 + co) * 9 + k];
        }
        __syncthreads();
#pragma unroll
        for (int q = 0; q < 4; q++) {
            for (int a = 0; a < nky; a++) {
                for (int e = 0; e < nkx; e++) {
                    float iv = s_in[q][threadIdx.y + dyA[a]][threadIdx.x + dxA[e]];
                    int k = kyA[a] * 3 + kxA[e];
#pragma unroll
                    for (int co = 0; co < 8; co++)
                        acc[co] = fmaf(iv, s_w[q][co][k], acc[co]);
                }
            }
        }
    }
    int y = 2 * (i0 + threadIdx.y) + py;
    int x = 2 * (j0 + threadIdx.x) + px;
    size_t ob = (((size_t)(b * 256 + cog * 8)) * 128 + y) * 128 + x;
#pragma unroll
    for (int co = 0; co < 8; co++) out[ob + (size_t)co * 16384] = acc[co];
}

// ---------------------------------------------------------------------------
// conv5 via tf32 mma.sync: reflect-pad conv 256->512 @128x128 + tanh.
// GEMM: D[cout, pix] = sum_{k=ci*9+t} W[cout,k] * P[k,pix]
// Block: 64 cout x 128 pixels (8 rows x 16 cols), 4 warps (2m x 2n),
// warp tile 32 cout x 64 pixels = 2 mtiles x 8 ntiles of m16n8k8.
// K chunks: 8 ci x 9 taps = 72 k per chunk, 32 chunks.
// grid (128 tiles, B, 8 cout groups), 128 threads.
// ---------------------------------------------------------------------------
__global__ __launch_bounds__(128) void k_conv5_mma(const float* __restrict__ in,
                                                   const float* __restrict__ w,
                                                   const float* __restrict__ bias,
                                                   float* __restrict__ out) {
    const int b = blockIdx.y;
    const int cog = blockIdx.z;               // 0..7, 64 couts each
    const int y0 = (blockIdx.x >> 3) * 8;
    const int x0 = (blockIdx.x & 7) * 16;

    const int tid = threadIdx.x;
    const int lane = tid & 31;
    const int ww = tid >> 5;
    const int mwarp = ww & 1;                 // 0/1 -> cout halves
    const int nwarp = ww >> 1;                // 0/1 -> pixel halves
    const int gid = lane >> 2;                // 0..7
    const int tig = lane & 3;                 // 0..3

    // halo: 8 ci x 10 rows x 18 cols, channel stride 184 (conflict-free frags)
    __shared__ unsigned s_in[8 * 184];
    __shared__ unsigned s_w[64 * 72];

    float acc[2][8][4];
#pragma unroll
    for (int mt = 0; mt < 2; mt++)
#pragma unroll
        for (int j = 0; j < 8; j++)
#pragma unroll
            for (int q = 0; q < 4; q++) acc[mt][j][q] = 0.f;

    const float* inb = in + (size_t)b * 256 * 16384;
    const float* wb = w + (size_t)cog * 64 * 2304;

    for (int cc = 0; cc < 32; cc++) {
        __syncthreads();
        // stage input halo (8 ci), tf32-rounded
        for (int idx = tid; idx < 8 * 180; idx += 128) {
            int c = idx / 180, r = idx - c * 180;
            int yy = r / 18, xx = r - yy * 18;
            int gy = refl(y0 - 1 + yy, 128);
            int gx = refl(x0 - 1 + xx, 128);
            s_in[c * 184 + yy * 18 + xx] =
                f2tf(inb[((size_t)(cc * 8 + c) * 128 + gy) * 128 + gx]);
        }
        // stage weights 64 x 72, tf32-rounded
        for (int idx = tid; idx < 64 * 72; idx += 128) {
            int co = idx / 72, kk = idx - co * 72;
            s_w[co * 72 + kk] = f2tf(wb[(size_t)co * 2304 + cc * 72 + kk]);
        }
        __syncthreads();

#pragma unroll
        for (int t = 0; t < 9; t++) {
            const int ky = t / 3, kx = t - ky * 3;
            // A fragments for 2 mtiles
            unsigned a[2][4];
#pragma unroll
            for (int mt = 0; mt < 2; mt++) {
                int mrow = mwarp * 32 + mt * 16 + gid;
                a[mt][0] = s_w[mrow * 72 + tig * 9 + t];
                a[mt][1] = s_w[(mrow + 8) * 72 + tig * 9 + t];
                a[mt][2] = s_w[mrow * 72 + (tig + 4) * 9 + t];
                a[mt][3] = s_w[(mrow + 8) * 72 + (tig + 4) * 9 + t];
            }
            // B fragments double-buffered over j
            unsigned bcur[2], bnxt[2];
            {
                int jj = nwarp * 8;
                int hy = (jj >> 1) + ky;
                int hx = (jj & 1) * 8 + gid + kx;
                bcur[0] = s_in[tig * 184 + hy * 18 + hx];
                bcur[1] = s_in[(tig + 4) * 184 + hy * 18 + hx];
            }
#pragma unroll
            for (int j = 0; j < 8; j++) {
                if (j < 7) {
                    int jj = nwarp * 8 + j + 1;
                    int hy = (jj >> 1) + ky;
                    int hx = (jj & 1) * 8 + gid + kx;
                    bnxt[0] = s_in[tig * 184 + hy * 18 + hx];
                    bnxt[1] = s_in[(tig + 4) * 184 + hy * 18 + hx];
                }
                mma_tf32(acc[0][j], a[0], bcur);
                mma_tf32(acc[1][j], a[1], bcur);
                bcur[0] = bnxt[0];
                bcur[1] = bnxt[1];
            }
        }
    }

    // epilogue: bias + tanh, float2 stores
    const int coutA = cog * 64 + mwarp * 32;
#pragma unroll
    for (int mt = 0; mt < 2; mt++) {
        int co0 = coutA + mt * 16 + gid;
        float bs0 = bias[co0];
        float bs1 = bias[co0 + 8];
#pragma unroll
        for (int j = 0; j < 8; j++) {
            int jj = nwarp * 8 + j;
            int y = y0 + (jj >> 1);
            int x = x0 + (jj & 1) * 8 + 2 * tig;
            float2 v0 = make_float2(tanhf(acc[mt][j][0] + bs0), tanhf(acc[mt][j][1] + bs0));
            float2 v1 = make_float2(tanhf(acc[mt][j][2] + bs1), tanhf(acc[mt][j][3] + bs1));
            *(float2*)&out[(((size_t)(b * 512 + co0)) * 128 + y) * 128 + x] = v0;
            *(float2*)&out[(((size_t)(b * 512 + co0 + 8)) * 128 + y) * 128 + x] = v1;
        }
    }
}

// ---------------------------------------------------------------------------
// labels + counts from segmap (nearest 256->128 = (2h,2w))
// ---------------------------------------------------------------------------
__global__ void k_label(const float* __restrict__ seg) {
    int b = blockIdx.y;
    int i = blockIdx.x * 256 + threadIdx.x;
    int h = i >> 7, wv = i & 127;
    const float* sp = seg + (size_t)b * NS * 65536 + (2 * h) * 256 + 2 * wv;
    int lab = 0;
#pragma unroll 1
    for (int s = 0; s < NS; s++) {
        if (sp[(size_t)s * 65536] > 0.f) { lab = s; break; }
    }
    g_label[b * 16384 + i] = lab;
    atomicAdd(&g_cnt[b * NS + lab], 1);
}

// ---------------------------------------------------------------------------
// segment-sum pooling
// ---------------------------------------------------------------------------
__global__ void k_pool(const float* __restrict__ codes) {
    int c = blockIdx.x & 511;
    int b = blockIdx.x >> 9;
    __shared__ float bins[NS * 8];
    if (threadIdx.x < NS * 8) bins[threadIdx.x] = 0.f;
    __syncthreads();
    const float* cp = codes + ((size_t)(b * 512 + c)) * 16384;
    const int* lp = g_label + b * 16384;
    int sub = threadIdx.x & 7;
    for (int i = threadIdx.x; i < 16384; i += 256)
        atomicAdd(&bins[lp[i] * 8 + sub], cp[i]);
    __syncthreads();
    if (threadIdx.x < NS) {
        float s = 0.f;
#pragma unroll
        for (int j = 0; j < 8; j++) s += bins[threadIdx.x * 8 + j];
        g_sums[((size_t)b * NS + threadIdx.x) * 512 + c] = s;
    }
}

// ---------------------------------------------------------------------------
__global__ void k_final(float* __restrict__ out) {
    int idx = blockIdx.x * 256 + threadIdx.x;
    if (idx >= NB * NS * 512) return;
    int bs = idx >> 9;
    int cnt = g_cnt[bs];
    out[idx] = cnt > 0 ? g_sums[idx] / (float)cnt : 0.f;
}

// ---------------------------------------------------------------------------
extern "C" void kernel_launch(void* const* d_in, const int* in_sizes, int n_in,
                              void* d_out, int out_size) {
    const float* input  = (const float*)d_in[0];
    const float* segmap = (const float*)d_in[1];
    const float* w1 = (const float*)d_in[2];
    const float* b1 = (const float*)d_in[3];
    const float* w2 = (const float*)d_in[4];
    const float* b2 = (const float*)d_in[5];
    const float* w3 = (const float*)d_in[6];
    const float* b3 = (const float*)d_in[7];
    const float* w4 = (const float*)d_in[8];
    const float* b4 = (const float*)d_in[9];
    const float* w5 = (const float*)d_in[10];
    const float* b5 = (const float*)d_in[11];
    float* out = (float*)d_out;

    float* act1;  cudaGetSymbolAddress((void**)&act1, g_act1);
    float* act2;  cudaGetSymbolAddress((void**)&act2, g_act2);
    float* act3;  cudaGetSymbolAddress((void**)&act3, g_act3);
    float* act4;  cudaGetSymbolAddress((void**)&act4, g_act4);
    float* codes; cudaGetSymbolAddress((void**)&codes, g_codes);

    k_zero_cnt<<<1, 256>>>();

    // L1
    k_conv1<<<dim3(256, NB * 32), 256>>>(input, w1, b1);
    k_in_lrelu<<<NB * 32, 256>>>(act1, 65536);
    // L2
    k_conv_s2<32, 64, 256><<<dim3(8, 8, NB * 8), dim3(16, 16)>>>(act1, w2, b2, act2);
    k_in_lrelu<<<NB * 64, 256>>>(act2, 16384);
    // L3
    k_conv_s2<64, 128, 128><<<dim3(4, 4, NB * 16), dim3(16, 16)>>>(act2, w3, b3, act3);
    k_in_lrelu<<<NB * 128, 256>>>(act3, 4096);
    // L4 (transposed conv)
    k_convT<<<dim3(4, 4, NB * 128), dim3(16, 16)>>>(act3, w4, b4, act4);
    k_in_lrelu<<<NB * 256, 256>>>(act4, 16384);
    // L5 (+tanh) via tf32 tensor cores
    k_conv5_mma<<<dim3(128, NB, 8), 128>>>(act4, w5, b5, codes);
    // pooling
    k_label<<<dim3(64, NB), 256>>>(segmap);
    k_pool<<<NB * 512, 256>>>(codes);
    k_final<<<(NB * NS * 512 + 255) / 256, 256>>>(out);
}

// round 3
// speedup vs baseline: 2.8356x; 1.3101x over previous
#include <cuda_runtime.h>
#include <cuda_bf16.h>
#include <math.h>

// ---------------------------------------------------------------------------
// B=8; input [8,3,256,256]; segmap [8,19,256,256]
// L1: reflect-pad conv 3->32, 256x256, IN, lrelu       (scalar)
// L2: conv s2 p1 32->64, 128x128, IN, lrelu            (scalar, smem-staged)
// L3: conv s2 p1 64->128, 64x64, IN, lrelu             (scalar, smem-staged)
// L4: convT s2 p1 op1 128->256, 128x128, IN, lrelu     (tf32 mma, per parity class)
// L5: reflect-pad conv 256->512, 128x128, tanh         (tf32 mma)
// pool: nearest one-hot segmap -> region means -> out [8,19,512]
// ---------------------------------------------------------------------------

#define NB 8
#define NS 19

__device__ float g_act1[NB * 32 * 256 * 256];
__device__ float g_act2[NB * 64 * 128 * 128];
__device__ float g_act3[NB * 128 * 64 * 64];
__device__ float g_act4[NB * 256 * 128 * 128];
__device__ float g_codes[(size_t)NB * 512 * 128 * 128];
__device__ int   g_label[NB * 128 * 128];
__device__ float g_sums[NB * NS * 512];
__device__ int   g_cnt[NB * NS];

__device__ __forceinline__ int refl(int v, int n) {
    return v < 0 ? -v : (v >= n ? 2 * n - 2 - v : v);
}

__device__ __forceinline__ unsigned f2tf(float f) {
    unsigned u;
    asm("cvt.rna.tf32.f32 %0, %1;" : "=r"(u) : "f"(f));
    return u;
}

__device__ __forceinline__ void mma_tf32(float* c, const unsigned* a, const unsigned* b) {
    asm volatile(
        "mma.sync.aligned.m16n8k8.row.col.f32.tf32.tf32.f32 "
        "{%0,%1,%2,%3}, {%4,%5,%6,%7}, {%8,%9}, {%0,%1,%2,%3};"
        : "+f"(c[0]), "+f"(c[1]), "+f"(c[2]), "+f"(c[3])
        : "r"(a[0]), "r"(a[1]), "r"(a[2]), "r"(a[3]), "r"(b[0]), "r"(b[1]));
}

// ---------------------------------------------------------------------------
__global__ void k_zero_cnt() {
    int i = threadIdx.x;
    if (i < NB * NS) g_cnt[i] = 0;
}

// ---------------------------------------------------------------------------
// conv1: reflect pad, 3->32, 256x256
// ---------------------------------------------------------------------------
__global__ void k_conv1(const float* __restrict__ in, const float* __restrict__ w,
                        const float* __restrict__ bias) {
    int p = blockIdx.y;
    int b = p >> 5, co = p & 31;
    __shared__ float ws[27];
    __shared__ float bs;
    if (threadIdx.x < 27) ws[threadIdx.x] = w[co * 27 + threadIdx.x];
    if (threadIdx.x == 0) bs = bias[co];
    __syncthreads();
    int idx = blockIdx.x * 256 + threadIdx.x;
    int y = idx >> 8, x = idx & 255;
    int ry[3], rx[3];
#pragma unroll
    for (int k = 0; k < 3; k++) { ry[k] = refl(y - 1 + k, 256); rx[k] = refl(x - 1 + k, 256); }
    float acc = bs;
#pragma unroll
    for (int ci = 0; ci < 3; ci++) {
        const float* ip = in + ((size_t)(b * 3 + ci)) * 65536;
#pragma unroll
        for (int ky = 0; ky < 3; ky++) {
            const float* row = ip + ry[ky] * 256;
#pragma unroll
            for (int kx = 0; kx < 3; kx++)
                acc = fmaf(row[rx[kx]], ws[ci * 9 + ky * 3 + kx], acc);
        }
    }
    g_act1[(size_t)p * 65536 + idx] = acc;
}

// ---------------------------------------------------------------------------
// fused instance-norm + leaky relu (in place)
// ---------------------------------------------------------------------------
__global__ void k_in_lrelu(float* __restrict__ buf, int HW) {
    float* p = buf + (size_t)blockIdx.x * HW;
    float s = 0.f, s2 = 0.f;
    for (int i = threadIdx.x; i < HW; i += 256) {
        float v = p[i];
        s += v;
        s2 = fmaf(v, v, s2);
    }
#pragma unroll
    for (int o = 16; o; o >>= 1) {
        s  += __shfl_down_sync(0xffffffffu, s, o);
        s2 += __shfl_down_sync(0xffffffffu, s2, o);
    }
    __shared__ float sh[16];
    __shared__ float mr[2];
    int wid = threadIdx.x >> 5, lid = threadIdx.x & 31;
    if (lid == 0) { sh[wid] = s; sh[8 + wid] = s2; }
    __syncthreads();
    if (threadIdx.x == 0) {
        float ts = 0.f, t2 = 0.f;
        for (int j = 0; j < 8; j++) { ts += sh[j]; t2 += sh[8 + j]; }
        float inv = 1.0f / (float)HW;
        float m = ts * inv;
        float var = t2 * inv - m * m;
        mr[0] = m;
        mr[1] = rsqrtf(var + 1e-5f);
    }
    __syncthreads();
    float m = mr[0], r = mr[1];
    for (int i = threadIdx.x; i < HW; i += 256) {
        float v = (p[i] - m) * r;
        p[i] = v > 0.f ? v : 0.2f * v;
    }
}

// ---------------------------------------------------------------------------
// strided conv (k=3, stride=2, pad=1), 8 couts per block, smem-staged input
// block (16,16); grid (HOUT/16, HOUT/16, NB*COUT/8)
// halo 33x33 per ci (zero-padded), 2 ci per chunk
// ---------------------------------------------------------------------------
template <int CIN, int COUT, int HIN>
__global__ void k_conv_s2(const float* __restrict__ in, const float* __restrict__ w,
                          const float* __restrict__ bias, float* __restrict__ out) {
    constexpr int HOUT = HIN / 2;
    int z = blockIdx.z;
    int b = z / (COUT / 8), cog = z % (COUT / 8);
    int tid = threadIdx.y * 16 + threadIdx.x;
    __shared__ float ws[8][CIN * 9];
    __shared__ float s_in[2][33 * 33];
    for (int idx = tid; idx < 8 * CIN * 9; idx += 256) {
        int co = idx / (CIN * 9), r = idx % (CIN * 9);
        ws[co][r] = w[(size_t)(cog * 8 + co) * CIN * 9 + r];
    }
    int oy0 = blockIdx.y * 16, ox0 = blockIdx.x * 16;
    float acc[8];
#pragma unroll
    for (int co = 0; co < 8; co++) acc[co] = bias[cog * 8 + co];
    const float* ibase = in + (size_t)b * CIN * HIN * HIN;

    for (int cc = 0; cc < CIN / 2; cc++) {
        __syncthreads();
        for (int idx = tid; idx < 2 * 1089; idx += 256) {
            int q = idx / 1089, r = idx - q * 1089;
            int rr = r / 33, cx = r - rr * 33;
            int gy = oy0 * 2 - 1 + rr;
            int gx = ox0 * 2 - 1 + cx;
            float v = ((unsigned)gy < (unsigned)HIN && (unsigned)gx < (unsigned)HIN)
                          ? ibase[((size_t)(cc * 2 + q) * HIN + gy) * HIN + gx]
                          : 0.f;
            s_in[q][r] = v;
        }
        __syncthreads();
#pragma unroll
        for (int q = 0; q < 2; q++) {
            float iv[9];
#pragma unroll
            for (int ky = 0; ky < 3; ky++)
#pragma unroll
                for (int kx = 0; kx < 3; kx++)
                    iv[ky * 3 + kx] = s_in[q][(2 * threadIdx.y + ky) * 33 + 2 * threadIdx.x + kx];
            int ci = cc * 2 + q;
#pragma unroll
            for (int co = 0; co < 8; co++) {
                float a = acc[co];
                const float* wp = &ws[co][ci * 9];
#pragma unroll
                for (int k = 0; k < 9; k++) a = fmaf(iv[k], wp[k], a);
                acc[co] = a;
            }
        }
    }
    int oy = oy0 + threadIdx.y, ox = ox0 + threadIdx.x;
    size_t ob = (((size_t)(b * COUT + cog * 8)) * HOUT + oy) * HOUT + ox;
#pragma unroll
    for (int co = 0; co < 8; co++) out[ob + (size_t)co * HOUT * HOUT] = acc[co];
}

// ---------------------------------------------------------------------------
// convT via tf32 mma: [B,128,64,64] -> [B,256,128,128]
// Per parity class (py,px): fixed tap set (1/2/2/4 taps). GEMM over class grid.
// Block: 64 cout x 128 class-pixels (8 rows x 16 cols), 4 warps (2m x 2n).
// K chunks: 8 ci per chunk, 16 chunks; tap loop outer.
// grid (32, NB, 16): z = cog*4 + cls. 128 threads.
// w layout (Cin=128, Cout=256, 3, 3)
// ---------------------------------------------------------------------------
__global__ __launch_bounds__(128) void k_convT_mma(const float* __restrict__ in,
                                                   const float* __restrict__ w,
                                                   const float* __restrict__ bias,
                                                   float* __restrict__ out) {
    const int b = blockIdx.y;
    const int z = blockIdx.z;
    const int cog = z >> 2, cls = z & 3;
    const int py = cls >> 1, px = cls & 1;
    const int y0 = (blockIdx.x >> 2) * 8;     // class-grid tile origin
    const int x0 = (blockIdx.x & 3) * 16;

    const int tid = threadIdx.x;
    const int lane = tid & 31;
    const int ww = tid >> 5;
    const int mwarp = ww & 1;
    const int nwarp = ww >> 1;
    const int gid = lane >> 2;
    const int tig = lane & 3;

    // tap tables
    int nky = py ? 2 : 1, nkx = px ? 2 : 1;
    int kyA[2] = {1, 0}, dyA[2] = {0, 0};
    if (py) { kyA[0] = 0; dyA[0] = 1; kyA[1] = 2; dyA[1] = 0; }
    int kxA[2] = {1, 0}, dxA[2] = {0, 0};
    if (px) { kxA[0] = 0; dxA[0] = 1; kxA[1] = 2; dxA[1] = 0; }
    const int ntaps = nky * nkx;
    int tval[4], tdy[4], tdx[4];
    for (int a = 0; a < nky; a++)
        for (int e = 0; e < nkx; e++) {
            int ta = a * nkx + e;
            tval[ta] = kyA[a] * 3 + kxA[e];
            tdy[ta] = dyA[a];
            tdx[ta] = dxA[e];
        }

    // smem: halo 8ci x (9 rows x 17 cols), ci stride 168 (168%32==8 -> no conflicts)
    __shared__ unsigned s_in[8 * 168];
    // weights [tap][64 co][8 ci] with co stride 12 (conflict-free A frags)
    __shared__ unsigned s_w[4 * 64 * 12];

    float acc[2][8][4];
#pragma unroll
    for (int mt = 0; mt < 2; mt++)
#pragma unroll
        for (int j = 0; j < 8; j++)
#pragma unroll
            for (int q = 0; q < 4; q++) acc[mt][j][q] = 0.f;

    const float* inb = in + (size_t)b * 128 * 4096;

    for (int cc = 0; cc < 16; cc++) {
        __syncthreads();
        // halo: rows y0..y0+8, cols x0..x0+16, zero beyond 64
        for (int idx = tid; idx < 8 * 153; idx += 128) {
            int c = idx / 153, r = idx - c * 153;
            int rr = r / 17, cx = r - rr * 17;
            int gy = y0 + rr, gx = x0 + cx;
            float v = (gy < 64 && gx < 64)
                          ? inb[((size_t)(cc * 8 + c) * 64 + gy) * 64 + gx]
                          : 0.f;
            s_in[c * 168 + rr * 17 + cx] = f2tf(v);
        }
        // weights for this chunk's 8 ci, only needed taps
        for (int idx = tid; idx < ntaps * 512; idx += 128) {
            int ta = idx >> 9;
            int rem = idx & 511;
            int co = rem >> 3, q = rem & 7;
            float v = w[(((size_t)(cc * 8 + q)) * 256 + cog * 64 + co) * 9 + tval[ta]];
            s_w[(ta * 64 + co) * 12 + q] = f2tf(v);
        }
        __syncthreads();

        for (int ta = 0; ta < ntaps; ta++) {
            unsigned a[2][4];
#pragma unroll
            for (int mt = 0; mt < 2; mt++) {
                int mrow = mwarp * 32 + mt * 16 + gid;
                a[mt][0] = s_w[(ta * 64 + mrow) * 12 + tig];
                a[mt][1] = s_w[(ta * 64 + mrow + 8) * 12 + tig];
                a[mt][2] = s_w[(ta * 64 + mrow) * 12 + tig + 4];
                a[mt][3] = s_w[(ta * 64 + mrow + 8) * 12 + tig + 4];
            }
            int dy = tdy[ta], dx = tdx[ta];
#pragma unroll
            for (int j = 0; j < 8; j++) {
                int jj = nwarp * 8 + j;
                int hy = (jj >> 1) + dy;
                int hx = (jj & 1) * 8 + gid + dx;
                unsigned bf[2];
                bf[0] = s_in[tig * 168 + hy * 17 + hx];
                bf[1] = s_in[(tig + 4) * 168 + hy * 17 + hx];
                mma_tf32(acc[0][j], a[0], bf);
                mma_tf32(acc[1][j], a[1], bf);
            }
        }
    }

    // epilogue: bias only (IN follows); scatter to parity positions
#pragma unroll
    for (int mt = 0; mt < 2; mt++) {
        int co0 = cog * 64 + mwarp * 32 + mt * 16 + gid;
        float bs0 = bias[co0];
        float bs1 = bias[co0 + 8];
#pragma unroll
        for (int j = 0; j < 8; j++) {
            int jj = nwarp * 8 + j;
            int yc = y0 + (jj >> 1);
            int xc = x0 + (jj & 1) * 8 + 2 * tig;
            int y = 2 * yc + py;
            int x = 2 * xc + px;
            size_t o0 = (((size_t)(b * 256 + co0)) * 128 + y) * 128 + x;
            size_t o1 = (((size_t)(b * 256 + co0 + 8)) * 128 + y) * 128 + x;
            out[o0] = acc[mt][j][0] + bs0;
            out[o0 + 2] = acc[mt][j][1] + bs0;
            out[o1] = acc[mt][j][2] + bs1;
            out[o1 + 2] = acc[mt][j][3] + bs1;
        }
    }
}

// ---------------------------------------------------------------------------
// conv5 via tf32 mma: reflect-pad conv 256->512 @128x128 + tanh.
// ---------------------------------------------------------------------------
__global__ __launch_bounds__(128) void k_conv5_mma(const float* __restrict__ in,
                                                   const float* __restrict__ w,
                                                   const float* __restrict__ bias,
                                                   float* __restrict__ out) {
    const int b = blockIdx.y;
    const int cog = blockIdx.z;
    const int y0 = (blockIdx.x >> 3) * 8;
    const int x0 = (blockIdx.x & 7) * 16;

    const int tid = threadIdx.x;
    const int lane = tid & 31;
    const int ww = tid >> 5;
    const int mwarp = ww & 1;
    const int nwarp = ww >> 1;
    const int gid = lane >> 2;
    const int tig = lane & 3;

    __shared__ unsigned s_in[8 * 184];
    __shared__ unsigned s_w[64 * 72];

    float acc[2][8][4];
#pragma unroll
    for (int mt = 0; mt < 2; mt++)
#pragma unroll
        for (int j = 0; j < 8; j++)
#pragma unroll
            for (int q = 0; q < 4; q++) acc[mt][j][q] = 0.f;

    const float* inb = in + (size_t)b * 256 * 16384;
    const float* wb = w + (size_t)cog * 64 * 2304;

    for (int cc = 0; cc < 32; cc++) {
        __syncthreads();
        for (int idx = tid; idx < 8 * 180; idx += 128) {
            int c = idx / 180, r = idx - c * 180;
            int yy = r / 18, xx = r - yy * 18;
            int gy = refl(y0 - 1 + yy, 128);
            int gx = refl(x0 - 1 + xx, 128);
            s_in[c * 184 + yy * 18 + xx] =
                f2tf(inb[((size_t)(cc * 8 + c) * 128 + gy) * 128 + gx]);
        }
        for (int idx = tid; idx < 64 * 72; idx += 128) {
            int co = idx / 72, kk = idx - co * 72;
            s_w[co * 72 + kk] = f2tf(wb[(size_t)co * 2304 + cc * 72 + kk]);
        }
        __syncthreads();

#pragma unroll
        for (int t = 0; t < 9; t++) {
            const int ky = t / 3, kx = t - ky * 3;
            unsigned a[2][4];
#pragma unroll
            for (int mt = 0; mt < 2; mt++) {
                int mrow = mwarp * 32 + mt * 16 + gid;
                a[mt][0] = s_w[mrow * 72 + tig * 9 + t];
                a[mt][1] = s_w[(mrow + 8) * 72 + tig * 9 + t];
                a[mt][2] = s_w[mrow * 72 + (tig + 4) * 9 + t];
                a[mt][3] = s_w[(mrow + 8) * 72 + (tig + 4) * 9 + t];
            }
            unsigned bcur[2], bnxt[2];
            {
                int jj = nwarp * 8;
                int hy = (jj >> 1) + ky;
                int hx = (jj & 1) * 8 + gid + kx;
                bcur[0] = s_in[tig * 184 + hy * 18 + hx];
                bcur[1] = s_in[(tig + 4) * 184 + hy * 18 + hx];
            }
#pragma unroll
            for (int j = 0; j < 8; j++) {
                if (j < 7) {
                    int jj = nwarp * 8 + j + 1;
                    int hy = (jj >> 1) + ky;
                    int hx = (jj & 1) * 8 + gid + kx;
                    bnxt[0] = s_in[tig * 184 + hy * 18 + hx];
                    bnxt[1] = s_in[(tig + 4) * 184 + hy * 18 + hx];
                }
                mma_tf32(acc[0][j], a[0], bcur);
                mma_tf32(acc[1][j], a[1], bcur);
                bcur[0] = bnxt[0];
                bcur[1] = bnxt[1];
            }
        }
    }

    const int coutA = cog * 64 + mwarp * 32;
#pragma unroll
    for (int mt = 0; mt < 2; mt++) {
        int co0 = coutA + mt * 16 + gid;
        float bs0 = bias[co0];
        float bs1 = bias[co0 + 8];
#pragma unroll
        for (int j = 0; j < 8; j++) {
            int jj = nwarp * 8 + j;
            int y = y0 + (jj >> 1);
            int x = x0 + (jj & 1) * 8 + 2 * tig;
            float2 v0 = make_float2(tanhf(acc[mt][j][0] + bs0), tanhf(acc[mt][j][1] + bs0));
            float2 v1 = make_float2(tanhf(acc[mt][j][2] + bs1), tanhf(acc[mt][j][3] + bs1));
            *(float2*)&out[(((size_t)(b * 512 + co0)) * 128 + y) * 128 + x] = v0;
            *(float2*)&out[(((size_t)(b * 512 + co0 + 8)) * 128 + y) * 128 + x] = v1;
        }
    }
}

// ---------------------------------------------------------------------------
// labels + counts (nearest 256->128 = (2h,2w))
// ---------------------------------------------------------------------------
__global__ void k_label(const float* __restrict__ seg) {
    int b = blockIdx.y;
    int i = blockIdx.x * 256 + threadIdx.x;
    int h = i >> 7, wv = i & 127;
    const float* sp = seg + (size_t)b * NS * 65536 + (2 * h) * 256 + 2 * wv;
    int lab = 0;
#pragma unroll 1
    for (int s = 0; s < NS; s++) {
        if (sp[(size_t)s * 65536] > 0.f) { lab = s; break; }
    }
    g_label[b * 16384 + i] = lab;
    atomicAdd(&g_cnt[b * NS + lab], 1);
}

// ---------------------------------------------------------------------------
// segment-sum pooling, vectorized
// ---------------------------------------------------------------------------
__global__ void k_pool(const float* __restrict__ codes) {
    int c = blockIdx.x & 511;
    int b = blockIdx.x >> 9;
    __shared__ float bins[NS * 8];
    if (threadIdx.x < NS * 8) bins[threadIdx.x] = 0.f;
    __syncthreads();
    const float4* cp = (const float4*)(codes + ((size_t)(b * 512 + c)) * 16384);
    const int4* lp = (const int4*)(g_label + b * 16384);
    int sub = threadIdx.x & 7;
    for (int i = threadIdx.x; i < 4096; i += 256) {
        float4 v = cp[i];
        int4 l = lp[i];
        atomicAdd(&bins[l.x * 8 + sub], v.x);
        atomicAdd(&bins[l.y * 8 + sub], v.y);
        atomicAdd(&bins[l.z * 8 + sub], v.z);
        atomicAdd(&bins[l.w * 8 + sub], v.w);
    }
    __syncthreads();
    if (threadIdx.x < NS) {
        float s = 0.f;
#pragma unroll
        for (int j = 0; j < 8; j++) s += bins[threadIdx.x * 8 + j];
        g_sums[((size_t)b * NS + threadIdx.x) * 512 + c] = s;
    }
}

// ---------------------------------------------------------------------------
__global__ void k_final(float* __restrict__ out) {
    int idx = blockIdx.x * 256 + threadIdx.x;
    if (idx >= NB * NS * 512) return;
    int bs = idx >> 9;
    int cnt = g_cnt[bs];
    out[idx] = cnt > 0 ? g_sums[idx] / (float)cnt : 0.f;
}

// ---------------------------------------------------------------------------
extern "C" void kernel_launch(void* const* d_in, const int* in_sizes, int n_in,
                              void* d_out, int out_size) {
    const float* input  = (const float*)d_in[0];
    const float* segmap = (const float*)d_in[1];
    const float* w1 = (const float*)d_in[2];
    const float* b1 = (const float*)d_in[3];
    const float* w2 = (const float*)d_in[4];
    const float* b2 = (const float*)d_in[5];
    const float* w3 = (const float*)d_in[6];
    const float* b3 = (const float*)d_in[7];
    const float* w4 = (const float*)d_in[8];
    const float* b4 = (const float*)d_in[9];
    const float* w5 = (const float*)d_in[10];
    const float* b5 = (const float*)d_in[11];
    float* out = (float*)d_out;

    float* act1;  cudaGetSymbolAddress((void**)&act1, g_act1);
    float* act2;  cudaGetSymbolAddress((void**)&act2, g_act2);
    float* act3;  cudaGetSymbolAddress((void**)&act3, g_act3);
    float* act4;  cudaGetSymbolAddress((void**)&act4, g_act4);
    float* codes; cudaGetSymbolAddress((void**)&codes, g_codes);

    k_zero_cnt<<<1, 256>>>();

    // L1
    k_conv1<<<dim3(256, NB * 32), 256>>>(input, w1, b1);
    k_in_lrelu<<<NB * 32, 256>>>(act1, 65536);
    // L2
    k_conv_s2<32, 64, 256><<<dim3(8, 8, NB * 8), dim3(16, 16)>>>(act1, w2, b2, act2);
    k_in_lrelu<<<NB * 64, 256>>>(act2, 16384);
    // L3
    k_conv_s2<64, 128, 128><<<dim3(4, 4, NB * 16), dim3(16, 16)>>>(act2, w3, b3, act3);
    k_in_lrelu<<<NB * 128, 256>>>(act3, 4096);
    // L4 (transposed conv, tf32 mma)
    k_convT_mma<<<dim3(32, NB, 16), 128>>>(act3, w4, b4, act4);
    k_in_lrelu<<<NB * 256, 256>>>(act4, 16384);
    // L5 (+tanh, tf32 mma)
    k_conv5_mma<<<dim3(128, NB, 8), 128>>>(act4, w5, b5, codes);
    // pooling
    k_label<<<dim3(64, NB), 256>>>(segmap);
    k_pool<<<NB * 512, 256>>>(codes);
    k_final<<<(NB * NS * 512 + 255) / 256, 256>>>(out);
}